// round 10
// baseline (speedup 1.0000x reference)
#include <cuda_runtime.h>
#include <cuda_fp16.h>
#include <cstdint>

// ---------------------------------------------------------------------------
// y[b,s,o] = sum_i x[b,s,i]*w[o,i] + bias[o],  w = (q-128)*scale (Q8_0)
// dtypes: x f32 [4,1024,4096], q i32 [4096,128,32], scales f32, bias f32
// -> out f32.  GEMM: A=x [M,K] f16, B=w [N,K] f16 (col-major for row.col),
// C [M,N] f32.  compute_103: no tcgen05 -> mma.sync + cp.async.
// R10: tile 128x128, 4 warps (64x64), BK=32 + 6-stage cp.async (SW64 smem),
// 2 CTA/SM. Deeper in-flight buffering vs LTS queueing. Prep kernels merged.
// ---------------------------------------------------------------------------

#define MAX_O 4096
#define MAX_K 4096
#define MAX_M 4096

__device__ __half g_w[(size_t)MAX_O * MAX_K];  // dequantized weights [N,K]
__device__ __half g_x[(size_t)MAX_M * MAX_K];  // f16 activations    [M,K]

// ---------------------------------------------------------------------------
// Merged prep: x f32->f16 and q i32->f16 dequant in one launch.
// Each thread handles 8 contiguous elements of one array.
// ---------------------------------------------------------------------------
__global__ void prep_kernel(const float* __restrict__ x,
                            const int* __restrict__ q,
                            const float* __restrict__ scales,
                            int nx_chunks, int O, int K) {
    int idx = blockIdx.x * blockDim.x + threadIdx.x;
    if (idx < nx_chunks) {
        size_t i = (size_t)idx * 8;
        const float4* xp = reinterpret_cast<const float4*>(x + i);
        float4 a = xp[0], b = xp[1];
        __half h[8];
        h[0] = __float2half(a.x); h[1] = __float2half(a.y);
        h[2] = __float2half(a.z); h[3] = __float2half(a.w);
        h[4] = __float2half(b.x); h[5] = __float2half(b.y);
        h[6] = __float2half(b.z); h[7] = __float2half(b.w);
        *reinterpret_cast<float4*>(&g_x[i]) = *reinterpret_cast<const float4*>(h);
        return;
    }
    int c = idx - nx_chunks;                    // dequant chunk id
    int chunks_per_row = K >> 3;
    if (c >= O * chunks_per_row) return;
    int o  = c / chunks_per_row;
    int k0 = (c - o * chunks_per_row) << 3;
    int nb = k0 >> 5;
    float s = scales[o * (K >> 5) + nb];

    const int4* qp = reinterpret_cast<const int4*>(q + (size_t)o * K + k0);
    int4 q0 = qp[0];
    int4 q1 = qp[1];

    __half h[8];
    h[0] = __float2half((float)(q0.x - 128) * s);
    h[1] = __float2half((float)(q0.y - 128) * s);
    h[2] = __float2half((float)(q0.z - 128) * s);
    h[3] = __float2half((float)(q0.w - 128) * s);
    h[4] = __float2half((float)(q1.x - 128) * s);
    h[5] = __float2half((float)(q1.y - 128) * s);
    h[6] = __float2half((float)(q1.z - 128) * s);
    h[7] = __float2half((float)(q1.w - 128) * s);

    *reinterpret_cast<float4*>(&g_w[(size_t)o * K + k0]) =
        *reinterpret_cast<const float4*>(h);
}

// ---------------------------------------------------------------------------
// GEMM: mma.sync m16n8k16, CTA 128x128x32, 4 warps (2x2) of 64x64 tiles,
// 6-stage cp.async, SW64 smem (64 B rows), rasterized grid, 2 CTA/SM.
// ---------------------------------------------------------------------------
constexpr int BM = 128, BN = 128, BK = 32;
constexpr int THREADS = 128;
constexpr int STAGES = 6;

constexpr int ROW_BYTES   = BK * 2;               // 64
constexpr int TILE_BYTES  = BM * ROW_BYTES;       // 8 KB each (A and B)
constexpr int STAGE_BYTES = 2 * TILE_BYTES;       // 16 KB
constexpr int SM_BIAS = 0;                        // BN f32 = 512 B
constexpr int SM_TILES = 1024;
constexpr int SMEM_TOTAL = SM_TILES + STAGES * STAGE_BYTES;  // ~97 KB

__device__ __forceinline__ uint32_t smem_u32(const void* p) {
    uint32_t a;
    asm("{ .reg .u64 t; cvta.to.shared.u64 t, %1; cvt.u32.u64 %0, t; }"
        : "=r"(a) : "l"(p));
    return a;
}
// SW64 swizzle: bits[5:4] ^= bits[8:7] (64-byte atom rows)
__device__ __forceinline__ uint32_t sw64(uint32_t off) {
    return off ^ ((off >> 3) & 0x30);
}
__device__ __forceinline__ void cp16(uint32_t saddr, const void* gaddr) {
    asm volatile("cp.async.cg.shared.global [%0], [%1], 16;"
                 :: "r"(saddr), "l"(gaddr));
}
__device__ __forceinline__ void cp_commit() {
    asm volatile("cp.async.commit_group;" ::: "memory");
}
__device__ __forceinline__ void cp_wait4() {
    asm volatile("cp.async.wait_group 4;" ::: "memory");
}
__device__ __forceinline__ void ldmx4(uint32_t* r, uint32_t addr) {
    asm volatile("ldmatrix.sync.aligned.m8n8.x4.shared.b16 {%0,%1,%2,%3}, [%4];"
                 : "=r"(r[0]), "=r"(r[1]), "=r"(r[2]), "=r"(r[3]) : "r"(addr));
}
__device__ __forceinline__ void mma16816(float* c, const uint32_t* a,
                                         const uint32_t* b) {
    asm volatile(
        "mma.sync.aligned.m16n8k16.row.col.f32.f16.f16.f32 "
        "{%0,%1,%2,%3}, {%4,%5,%6,%7}, {%8,%9}, {%0,%1,%2,%3};"
        : "+f"(c[0]), "+f"(c[1]), "+f"(c[2]), "+f"(c[3])
        : "r"(a[0]), "r"(a[1]), "r"(a[2]), "r"(a[3]), "r"(b[0]), "r"(b[1]));
}

__global__ void __launch_bounds__(THREADS, 2)
gemm_mma_kernel(const float* __restrict__ bias,
                float* __restrict__ C, int M, int N, int K) {
    extern __shared__ char smem[];
    const uint32_t sb_tiles = smem_u32(smem + SM_TILES);
    const int tid  = threadIdx.x;
    const int wid  = tid >> 5;
    const int lane = tid & 31;

    // Threadblock rasterization: GROUP M-tiles per N-column sweep (L2 reuse)
    const int nbx = gridDim.x;            // N tiles
    const int nby = gridDim.y;            // M tiles
    int bid = blockIdx.y * nbx + blockIdx.x;
    constexpr int GROUP = 16;
    int tiles_per_group = GROUP * nbx;
    int g    = bid / tiles_per_group;
    int rem  = bid - g * tiles_per_group;
    int gm   = g * GROUP;
    int gsz  = (nby - gm) < GROUP ? (nby - gm) : GROUP;
    const int bm = (gm + rem % gsz) * BM;
    const int bn = (rem / gsz) * BN;

    const int wm_off = (wid >> 1) * 64;   // 0 or 64
    const int wn_off = (wid & 1) * 64;    // 0 or 64

    float* bias_s = (float*)(smem + SM_BIAS);
    if (tid < BN) bias_s[tid] = bias[bn + tid];

    const __half* Ag = g_x + (size_t)bm * K;
    const __half* Bg = g_w + (size_t)bn * K;

    // Loader: 128 rows x 64 B per tile; 4 chunks of 16B per thread per tile.
    const int lr = tid >> 2;          // base row 0..31 (stride 32)
    const int lcb = (tid & 3) * 16;   // byte offset within 64-B row
    const int lce = (tid & 3) * 8;    // element offset

    auto load_stage = [&](int stage, int kblk) {
        uint32_t a_s = sb_tiles + stage * STAGE_BYTES;
        uint32_t b_s = a_s + TILE_BYTES;
#pragma unroll
        for (int i = 0; i < 4; i++) {
            int r = lr + i * 32;
            cp16(a_s + sw64(r * ROW_BYTES + lcb), Ag + (size_t)r * K + kblk + lce);
        }
#pragma unroll
        for (int i = 0; i < 4; i++) {
            int r = lr + i * 32;
            cp16(b_s + sw64(r * ROW_BYTES + lcb), Bg + (size_t)r * K + kblk + lce);
        }
        cp_commit();
    };

    float acc[4][8][4];
#pragma unroll
    for (int mi = 0; mi < 4; mi++)
#pragma unroll
        for (int ni = 0; ni < 8; ni++)
#pragma unroll
            for (int e = 0; e < 4; e++) acc[mi][ni][e] = 0.0f;

    const int iters = K / BK;     // 128

    // Prologue: fill STAGES-1 stages
#pragma unroll
    for (int s = 0; s < STAGES - 1; s++)
        load_stage(s, s * BK);

    // ldmatrix lane addressing
    const int a_row_l = lane & 15;
    const int a_chk_l = lane >> 4;               // 0..1
    const int b_row_l = (lane & 7) + ((lane >> 4) << 3);
    const int b_chk_l = (lane >> 3) & 1;

    for (int it = 0; it < iters; ++it) {
        cp_wait4();
        __syncthreads();

        if (it + STAGES - 1 < iters)
            load_stage((it + STAGES - 1) % STAGES, (it + STAGES - 1) * BK);
        else
            cp_commit();  // keep group counting aligned

        uint32_t a_s = sb_tiles + (it % STAGES) * STAGE_BYTES;
        uint32_t b_s = a_s + TILE_BYTES;

#pragma unroll
        for (int ks = 0; ks < BK / 16; ks++) {
            uint32_t afrag[4][4];
            uint32_t bfrag[4][4];
#pragma unroll
            for (int mi = 0; mi < 4; mi++) {
                int row = wm_off + mi * 16 + a_row_l;
                ldmx4(afrag[mi],
                      a_s + sw64(row * ROW_BYTES + ks * 32 + a_chk_l * 16));
            }
#pragma unroll
            for (int nj = 0; nj < 4; nj++) {
                int row = wn_off + nj * 16 + b_row_l;
                ldmx4(bfrag[nj],
                      b_s + sw64(row * ROW_BYTES + ks * 32 + b_chk_l * 16));
            }
#pragma unroll
            for (int mi = 0; mi < 4; mi++)
#pragma unroll
                for (int ni = 0; ni < 8; ni++)
                    mma16816(acc[mi][ni], afrag[mi], &bfrag[ni >> 1][(ni & 1) * 2]);
        }
    }

    // Epilogue: registers -> global, fused bias, float2 stores
#pragma unroll
    for (int mi = 0; mi < 4; mi++) {
        int r0 = bm + wm_off + mi * 16 + (lane >> 2);
#pragma unroll
        for (int ni = 0; ni < 8; ni++) {
            int col  = wn_off + ni * 8 + (lane & 3) * 2;
            float b0 = bias_s[col], b1 = bias_s[col + 1];
            float2 v0 = make_float2(acc[mi][ni][0] + b0, acc[mi][ni][1] + b1);
            float2 v1 = make_float2(acc[mi][ni][2] + b0, acc[mi][ni][3] + b1);
            *reinterpret_cast<float2*>(C + (size_t)r0 * N + bn + col) = v0;
            *reinterpret_cast<float2*>(C + (size_t)(r0 + 8) * N + bn + col) = v1;
        }
    }
}

// ---------------------------------------------------------------------------
// Launch
// ---------------------------------------------------------------------------
extern "C" void kernel_launch(void* const* d_in, const int* in_sizes, int n_in,
                              void* d_out, int out_size) {
    const float* x      = (const float*)d_in[0];
    const int*   q      = (const int*)  d_in[1];
    const float* scales = (const float*)d_in[2];
    const float* bias   = (const float*)d_in[3];
    float*       out    = (float*)d_out;

    const int O = in_sizes[3];                 // 4096
    const int K = in_sizes[1] / O;             // 4096
    const int M = in_sizes[0] / K;             // 4096
    const int N = O;

    int nx_chunks = (int)((size_t)M * K / 8);
    int nq_chunks = O * (K >> 3);
    int total = nx_chunks + nq_chunks;
    prep_kernel<<<(total + 255) / 256, 256>>>(x, q, scales, nx_chunks, O, K);

    cudaFuncSetAttribute(gemm_mma_kernel,
                         cudaFuncAttributeMaxDynamicSharedMemorySize, SMEM_TOTAL);
    dim3 grid(N / BN, M / BM);
    gemm_mma_kernel<<<grid, THREADS, SMEM_TOTAL>>>(bias, out, M, N, K);
}

// round 11
// speedup vs baseline: 1.0873x; 1.0873x over previous
#include <cuda_runtime.h>
#include <cuda_fp16.h>
#include <cstdint>

// ---------------------------------------------------------------------------
// y[b,s,o] = sum_i x[b,s,i]*w[o,i] + bias[o],  w = (q-128)*scale (Q8_0)
// dtypes: x f32 [4,1024,4096], q i32 [4096,128,32], scales f32, bias f32
// -> out f32.  GEMM: A=x [M,K] f16, B=w [N,K] f16 (col-major for row.col),
// C [M,N] f32.  compute_103: no tcgen05 -> mma.sync + cp.async.
// R11: champion R7 config (128x128x64, 4 warps 64x64, 3-stage, 2 CTA/SM,
// GROUP=16) + merged prep + cp.async issue interleaved across ks steps.
// ---------------------------------------------------------------------------

#define MAX_O 4096
#define MAX_K 4096
#define MAX_M 4096

__device__ __half g_w[(size_t)MAX_O * MAX_K];  // dequantized weights [N,K]
__device__ __half g_x[(size_t)MAX_M * MAX_K];  // f16 activations    [M,K]

// ---------------------------------------------------------------------------
// Merged prep: x f32->f16 and q i32->f16 dequant in one launch.
// ---------------------------------------------------------------------------
__global__ void prep_kernel(const float* __restrict__ x,
                            const int* __restrict__ q,
                            const float* __restrict__ scales,
                            int nx_chunks, int O, int K) {
    int idx = blockIdx.x * blockDim.x + threadIdx.x;
    if (idx < nx_chunks) {
        size_t i = (size_t)idx * 8;
        const float4* xp = reinterpret_cast<const float4*>(x + i);
        float4 a = xp[0], b = xp[1];
        __half h[8];
        h[0] = __float2half(a.x); h[1] = __float2half(a.y);
        h[2] = __float2half(a.z); h[3] = __float2half(a.w);
        h[4] = __float2half(b.x); h[5] = __float2half(b.y);
        h[6] = __float2half(b.z); h[7] = __float2half(b.w);
        *reinterpret_cast<float4*>(&g_x[i]) = *reinterpret_cast<const float4*>(h);
        return;
    }
    int c = idx - nx_chunks;
    int chunks_per_row = K >> 3;
    if (c >= O * chunks_per_row) return;
    int o  = c / chunks_per_row;
    int k0 = (c - o * chunks_per_row) << 3;
    int nb = k0 >> 5;
    float s = scales[o * (K >> 5) + nb];

    const int4* qp = reinterpret_cast<const int4*>(q + (size_t)o * K + k0);
    int4 q0 = qp[0];
    int4 q1 = qp[1];

    __half h[8];
    h[0] = __float2half((float)(q0.x - 128) * s);
    h[1] = __float2half((float)(q0.y - 128) * s);
    h[2] = __float2half((float)(q0.z - 128) * s);
    h[3] = __float2half((float)(q0.w - 128) * s);
    h[4] = __float2half((float)(q1.x - 128) * s);
    h[5] = __float2half((float)(q1.y - 128) * s);
    h[6] = __float2half((float)(q1.z - 128) * s);
    h[7] = __float2half((float)(q1.w - 128) * s);

    *reinterpret_cast<float4*>(&g_w[(size_t)o * K + k0]) =
        *reinterpret_cast<const float4*>(h);
}

// ---------------------------------------------------------------------------
// GEMM: mma.sync m16n8k16, CTA 128x128x64, 4 warps (2x2) of 64x64 tiles,
// 3-stage cp.async (issue interleaved with MMAs), SW128 smem, raster grid.
// ---------------------------------------------------------------------------
constexpr int BM = 128, BN = 128, BK = 64;
constexpr int THREADS = 128;
constexpr int STAGES = 3;

constexpr int TILE_BYTES  = BM * 128;             // 16 KB each (A and B)
constexpr int STAGE_BYTES = 2 * TILE_BYTES;       // 32 KB
constexpr int SM_BIAS = 0;                        // BN f32 = 512 B
constexpr int SM_TILES = 1024;
constexpr int SMEM_TOTAL = SM_TILES + STAGES * STAGE_BYTES;  // 97.5 KB

__device__ __forceinline__ uint32_t smem_u32(const void* p) {
    uint32_t a;
    asm("{ .reg .u64 t; cvta.to.shared.u64 t, %1; cvt.u32.u64 %0, t; }"
        : "=r"(a) : "l"(p));
    return a;
}
__device__ __forceinline__ uint32_t sw128(uint32_t off) {
    return off ^ ((off >> 3) & 0x70);
}
__device__ __forceinline__ void cp16(uint32_t saddr, const void* gaddr) {
    asm volatile("cp.async.cg.shared.global [%0], [%1], 16;"
                 :: "r"(saddr), "l"(gaddr));
}
__device__ __forceinline__ void cp_commit() {
    asm volatile("cp.async.commit_group;" ::: "memory");
}
__device__ __forceinline__ void cp_wait1() {
    asm volatile("cp.async.wait_group 1;" ::: "memory");
}
__device__ __forceinline__ void ldmx4(uint32_t* r, uint32_t addr) {
    asm volatile("ldmatrix.sync.aligned.m8n8.x4.shared.b16 {%0,%1,%2,%3}, [%4];"
                 : "=r"(r[0]), "=r"(r[1]), "=r"(r[2]), "=r"(r[3]) : "r"(addr));
}
__device__ __forceinline__ void mma16816(float* c, const uint32_t* a,
                                         const uint32_t* b) {
    asm volatile(
        "mma.sync.aligned.m16n8k16.row.col.f32.f16.f16.f32 "
        "{%0,%1,%2,%3}, {%4,%5,%6,%7}, {%8,%9}, {%0,%1,%2,%3};"
        : "+f"(c[0]), "+f"(c[1]), "+f"(c[2]), "+f"(c[3])
        : "r"(a[0]), "r"(a[1]), "r"(a[2]), "r"(a[3]), "r"(b[0]), "r"(b[1]));
}

__global__ void __launch_bounds__(THREADS, 2)
gemm_mma_kernel(const float* __restrict__ bias,
                float* __restrict__ C, int M, int N, int K) {
    extern __shared__ char smem[];
    const uint32_t sb_tiles = smem_u32(smem + SM_TILES);
    const int tid  = threadIdx.x;
    const int wid  = tid >> 5;
    const int lane = tid & 31;

    // Threadblock rasterization: GROUP M-tiles per N-column sweep (L2 reuse)
    const int nbx = gridDim.x;
    const int nby = gridDim.y;
    int bid = blockIdx.y * nbx + blockIdx.x;
    constexpr int GROUP = 16;
    int tiles_per_group = GROUP * nbx;
    int g    = bid / tiles_per_group;
    int rem  = bid - g * tiles_per_group;
    int gm   = g * GROUP;
    int gsz  = (nby - gm) < GROUP ? (nby - gm) : GROUP;
    const int bm = (gm + rem % gsz) * BM;
    const int bn = (rem / gsz) * BN;

    const int wm_off = (wid >> 1) * 64;   // 0 or 64
    const int wn_off = (wid & 1) * 64;    // 0 or 64

    float* bias_s = (float*)(smem + SM_BIAS);

    const __half* Ag = g_x + (size_t)bm * K;
    const __half* Bg = g_w + (size_t)bn * K;

    const int lr  = tid >> 3;        // base row 0..15 (stride 16)
    const int lce = (tid & 7) * 8;   // element offset within 64-wide k-row
    const int lcb = (tid & 7) * 16;  // byte offset (pre-swizzle)

    // Full-burst loader for the prologue stages
    auto load_stage = [&](int stage, int kblk) {
        uint32_t a_s = sb_tiles + stage * STAGE_BYTES;
        uint32_t b_s = a_s + TILE_BYTES;
#pragma unroll
        for (int i = 0; i < 8; i++) {
            int r = lr + i * 16;
            cp16(a_s + sw128(r * 128 + lcb), Ag + (size_t)r * K + kblk + lce);
        }
#pragma unroll
        for (int i = 0; i < 8; i++) {
            int r = lr + i * 16;
            cp16(b_s + sw128(r * 128 + lcb), Bg + (size_t)r * K + kblk + lce);
        }
        cp_commit();
    };

    float acc[4][8][4];
#pragma unroll
    for (int mi = 0; mi < 4; mi++)
#pragma unroll
        for (int ni = 0; ni < 8; ni++)
#pragma unroll
            for (int e = 0; e < 4; e++) acc[mi][ni][e] = 0.0f;

    if (tid < BN) bias_s[tid] = bias[bn + tid];

    load_stage(0, 0);
    load_stage(1, BK);

    const int iters = K / BK;     // 64

    // ldmatrix lane addressing
    const int a_row_l = lane & 15;
    const int a_chk_l = lane >> 4;               // 0..1
    const int b_row_l = (lane & 7) + ((lane >> 4) << 3);
    const int b_chk_l = (lane >> 3) & 1;

    for (int it = 0; it < iters; ++it) {
        cp_wait1();
        __syncthreads();

        uint32_t a_s = sb_tiles + (it % STAGES) * STAGE_BYTES;
        uint32_t b_s = a_s + TILE_BYTES;

        // Next-next stage to load, interleaved into the ks loop below
        const int it2 = it + STAGES - 1;
        const bool do_load = (it2 < iters);
        const int  st2 = it2 % STAGES;
        const uint32_t a_d = sb_tiles + st2 * STAGE_BYTES;
        const uint32_t b_d = a_d + TILE_BYTES;
        const int kblk2 = it2 * BK;

#pragma unroll
        for (int ks = 0; ks < BK / 16; ks++) {
            uint32_t afrag[4][4];
            uint32_t bfrag[4][4];
#pragma unroll
            for (int mi = 0; mi < 4; mi++) {
                int row = wm_off + mi * 16 + a_row_l;
                ldmx4(afrag[mi],
                      a_s + sw128(row * 128 + ks * 32 + a_chk_l * 16));
            }
#pragma unroll
            for (int nj = 0; nj < 4; nj++) {
                int row = wn_off + nj * 16 + b_row_l;
                ldmx4(bfrag[nj],
                      b_s + sw128(row * 128 + ks * 32 + b_chk_l * 16));
            }

            // Interleave 4 of the 16 cp.asyncs for stage it+2
            if (do_load) {
#pragma unroll
                for (int i = 2 * ks; i < 2 * ks + 2; i++) {
                    int r = lr + i * 16;
                    cp16(a_d + sw128(r * 128 + lcb),
                         Ag + (size_t)r * K + kblk2 + lce);
                    cp16(b_d + sw128(r * 128 + lcb),
                         Bg + (size_t)r * K + kblk2 + lce);
                }
            }

#pragma unroll
            for (int mi = 0; mi < 4; mi++)
#pragma unroll
                for (int ni = 0; ni < 8; ni++)
                    mma16816(acc[mi][ni], afrag[mi], &bfrag[ni >> 1][(ni & 1) * 2]);
        }
        cp_commit();   // one group per iteration (empty on tail iters)
    }

    // Epilogue: registers -> global, fused bias, float2 stores
#pragma unroll
    for (int mi = 0; mi < 4; mi++) {
        int r0 = bm + wm_off + mi * 16 + (lane >> 2);
#pragma unroll
        for (int ni = 0; ni < 8; ni++) {
            int col  = wn_off + ni * 8 + (lane & 3) * 2;
            float b0 = bias_s[col], b1 = bias_s[col + 1];
            float2 v0 = make_float2(acc[mi][ni][0] + b0, acc[mi][ni][1] + b1);
            float2 v1 = make_float2(acc[mi][ni][2] + b0, acc[mi][ni][3] + b1);
            *reinterpret_cast<float2*>(C + (size_t)r0 * N + bn + col) = v0;
            *reinterpret_cast<float2*>(C + (size_t)(r0 + 8) * N + bn + col) = v1;
        }
    }
}

// ---------------------------------------------------------------------------
// Launch
// ---------------------------------------------------------------------------
extern "C" void kernel_launch(void* const* d_in, const int* in_sizes, int n_in,
                              void* d_out, int out_size) {
    const float* x      = (const float*)d_in[0];
    const int*   q      = (const int*)  d_in[1];
    const float* scales = (const float*)d_in[2];
    const float* bias   = (const float*)d_in[3];
    float*       out    = (float*)d_out;

    const int O = in_sizes[3];                 // 4096
    const int K = in_sizes[1] / O;             // 4096
    const int M = in_sizes[0] / K;             // 4096
    const int N = O;

    int nx_chunks = (int)((size_t)M * K / 8);
    int nq_chunks = O * (K >> 3);
    int total = nx_chunks + nq_chunks;
    prep_kernel<<<(total + 255) / 256, 256>>>(x, q, scales, nx_chunks, O, K);

    cudaFuncSetAttribute(gemm_mma_kernel,
                         cudaFuncAttributeMaxDynamicSharedMemorySize, SMEM_TOTAL);
    dim3 grid(N / BN, M / BM);
    gemm_mma_kernel<<<grid, THREADS, SMEM_TOTAL>>>(bias, out, M, N, K);
}

// round 12
// speedup vs baseline: 1.1536x; 1.0609x over previous
#include <cuda_runtime.h>
#include <cuda_fp16.h>
#include <cstdint>

// ---------------------------------------------------------------------------
// y[b,s,o] = sum_i x[b,s,i]*w[o,i] + bias[o],  w = (q-128)*scale (Q8_0)
// dtypes: x f32 [4,1024,4096], q i32 [4096,128,32], scales f32, bias f32
// -> out f32.  GEMM: A=x [M,K] f16, B=w [N,K] f16 (col-major for row.col),
// C [M,N] f32.  compute_103: no tcgen05 -> mma.sync + cp.async.
// R12: champion R7 GEMM (128x128x64, 4 warps 64x64, 3-stage, 2 CTA/SM,
// GROUP=16, dbuf ldmatrix) + single merged prep kernel.
// GEMM is smem-crossbar bound (~75%) per R11 ncu; tensor=68%.
// ---------------------------------------------------------------------------

#define MAX_O 4096
#define MAX_K 4096
#define MAX_M 4096

__device__ __half g_w[(size_t)MAX_O * MAX_K];  // dequantized weights [N,K]
__device__ __half g_x[(size_t)MAX_M * MAX_K];  // f16 activations    [M,K]

// ---------------------------------------------------------------------------
// Merged prep: x f32->f16 and q i32->f16 dequant in one launch.
// ---------------------------------------------------------------------------
__global__ void prep_kernel(const float* __restrict__ x,
                            const int* __restrict__ q,
                            const float* __restrict__ scales,
                            int nx_chunks, int O, int K) {
    int idx = blockIdx.x * blockDim.x + threadIdx.x;
    if (idx < nx_chunks) {
        size_t i = (size_t)idx * 8;
        const float4* xp = reinterpret_cast<const float4*>(x + i);
        float4 a = xp[0], b = xp[1];
        __half h[8];
        h[0] = __float2half(a.x); h[1] = __float2half(a.y);
        h[2] = __float2half(a.z); h[3] = __float2half(a.w);
        h[4] = __float2half(b.x); h[5] = __float2half(b.y);
        h[6] = __float2half(b.z); h[7] = __float2half(b.w);
        *reinterpret_cast<float4*>(&g_x[i]) = *reinterpret_cast<const float4*>(h);
        return;
    }
    int c = idx - nx_chunks;
    int chunks_per_row = K >> 3;
    if (c >= O * chunks_per_row) return;
    int o  = c / chunks_per_row;
    int k0 = (c - o * chunks_per_row) << 3;
    int nb = k0 >> 5;
    float s = scales[o * (K >> 5) + nb];

    const int4* qp = reinterpret_cast<const int4*>(q + (size_t)o * K + k0);
    int4 q0 = qp[0];
    int4 q1 = qp[1];

    __half h[8];
    h[0] = __float2half((float)(q0.x - 128) * s);
    h[1] = __float2half((float)(q0.y - 128) * s);
    h[2] = __float2half((float)(q0.z - 128) * s);
    h[3] = __float2half((float)(q0.w - 128) * s);
    h[4] = __float2half((float)(q1.x - 128) * s);
    h[5] = __float2half((float)(q1.y - 128) * s);
    h[6] = __float2half((float)(q1.z - 128) * s);
    h[7] = __float2half((float)(q1.w - 128) * s);

    *reinterpret_cast<float4*>(&g_w[(size_t)o * K + k0]) =
        *reinterpret_cast<const float4*>(h);
}

// ---------------------------------------------------------------------------
// GEMM: mma.sync m16n8k16, CTA 128x128x64, 4 warps (2x2) of 64x64 tiles,
// 3-stage cp.async, SW128 smem, double-buffered ldmatrix, rasterized grid.
// ---------------------------------------------------------------------------
constexpr int BM = 128, BN = 128, BK = 64;
constexpr int THREADS = 128;
constexpr int STAGES = 3;

constexpr int TILE_BYTES  = BM * 128;             // 16 KB each (A and B)
constexpr int STAGE_BYTES = 2 * TILE_BYTES;       // 32 KB
constexpr int SM_BIAS = 0;                        // BN f32 = 512 B
constexpr int SM_TILES = 1024;
constexpr int SMEM_TOTAL = SM_TILES + STAGES * STAGE_BYTES;  // 97.5 KB

__device__ __forceinline__ uint32_t smem_u32(const void* p) {
    uint32_t a;
    asm("{ .reg .u64 t; cvta.to.shared.u64 t, %1; cvt.u32.u64 %0, t; }"
        : "=r"(a) : "l"(p));
    return a;
}
__device__ __forceinline__ uint32_t sw128(uint32_t off) {
    return off ^ ((off >> 3) & 0x70);
}
__device__ __forceinline__ void cp16(uint32_t saddr, const void* gaddr) {
    asm volatile("cp.async.cg.shared.global [%0], [%1], 16;"
                 :: "r"(saddr), "l"(gaddr));
}
__device__ __forceinline__ void cp_commit() {
    asm volatile("cp.async.commit_group;" ::: "memory");
}
__device__ __forceinline__ void cp_wait1() {
    asm volatile("cp.async.wait_group 1;" ::: "memory");
}
__device__ __forceinline__ void ldmx4(uint32_t* r, uint32_t addr) {
    asm volatile("ldmatrix.sync.aligned.m8n8.x4.shared.b16 {%0,%1,%2,%3}, [%4];"
                 : "=r"(r[0]), "=r"(r[1]), "=r"(r[2]), "=r"(r[3]) : "r"(addr));
}
__device__ __forceinline__ void mma16816(float* c, const uint32_t* a,
                                         const uint32_t* b) {
    asm volatile(
        "mma.sync.aligned.m16n8k16.row.col.f32.f16.f16.f32 "
        "{%0,%1,%2,%3}, {%4,%5,%6,%7}, {%8,%9}, {%0,%1,%2,%3};"
        : "+f"(c[0]), "+f"(c[1]), "+f"(c[2]), "+f"(c[3])
        : "r"(a[0]), "r"(a[1]), "r"(a[2]), "r"(a[3]), "r"(b[0]), "r"(b[1]));
}

__global__ void __launch_bounds__(THREADS, 2)
gemm_mma_kernel(const float* __restrict__ bias,
                float* __restrict__ C, int M, int N, int K) {
    extern __shared__ char smem[];
    const uint32_t sb_tiles = smem_u32(smem + SM_TILES);
    const int tid  = threadIdx.x;
    const int wid  = tid >> 5;
    const int lane = tid & 31;

    // Threadblock rasterization: GROUP M-tiles per N-column sweep (L2 reuse)
    const int nbx = gridDim.x;
    const int nby = gridDim.y;
    int bid = blockIdx.y * nbx + blockIdx.x;
    constexpr int GROUP = 16;
    int tiles_per_group = GROUP * nbx;
    int g    = bid / tiles_per_group;
    int rem  = bid - g * tiles_per_group;
    int gm   = g * GROUP;
    int gsz  = (nby - gm) < GROUP ? (nby - gm) : GROUP;
    const int bm = (gm + rem % gsz) * BM;
    const int bn = (rem / gsz) * BN;

    const int wm_off = (wid >> 1) * 64;   // 0 or 64
    const int wn_off = (wid & 1) * 64;    // 0 or 64

    float* bias_s = (float*)(smem + SM_BIAS);
    if (tid < BN) bias_s[tid] = bias[bn + tid];

    const __half* Ag = g_x + (size_t)bm * K;
    const __half* Bg = g_w + (size_t)bn * K;

    const int lr = tid >> 3;        // base row 0..15 (stride 16)
    const int lc = (tid & 7) * 8;   // element offset within 64-wide k-row

    auto load_stage = [&](int stage, int kblk) {
        uint32_t a_s = sb_tiles + stage * STAGE_BYTES;
        uint32_t b_s = a_s + TILE_BYTES;
#pragma unroll
        for (int i = 0; i < 8; i++) {
            int r = lr + i * 16;
            cp16(a_s + sw128(r * 128 + lc * 2), Ag + (size_t)r * K + kblk + lc);
        }
#pragma unroll
        for (int i = 0; i < 8; i++) {
            int r = lr + i * 16;
            cp16(b_s + sw128(r * 128 + lc * 2), Bg + (size_t)r * K + kblk + lc);
        }
        cp_commit();
    };

    float acc[4][8][4];
#pragma unroll
    for (int mi = 0; mi < 4; mi++)
#pragma unroll
        for (int ni = 0; ni < 8; ni++)
#pragma unroll
            for (int e = 0; e < 4; e++) acc[mi][ni][e] = 0.0f;

    load_stage(0, 0);
    load_stage(1, BK);

    const int iters = K / BK;     // 64

    // ldmatrix lane addressing
    const int a_row_l = lane & 15;
    const int a_chk_l = lane >> 4;               // 0..1
    const int b_row_l = (lane & 7) + ((lane >> 4) << 3);
    const int b_chk_l = (lane >> 3) & 1;

    uint32_t afrag[2][4][4];
    uint32_t bfrag[2][4][4];

    for (int it = 0; it < iters; ++it) {
        cp_wait1();
        __syncthreads();

        if (it + STAGES - 1 < iters)
            load_stage((it + STAGES - 1) % STAGES, (it + STAGES - 1) * BK);
        else
            cp_commit();  // keep group counting aligned

        uint32_t a_s = sb_tiles + (it % STAGES) * STAGE_BYTES;
        uint32_t b_s = a_s + TILE_BYTES;

        // Prefetch ks=0 fragments
#pragma unroll
        for (int mi = 0; mi < 4; mi++) {
            int row = wm_off + mi * 16 + a_row_l;
            ldmx4(afrag[0][mi], a_s + sw128(row * 128 + a_chk_l * 16));
        }
#pragma unroll
        for (int nj = 0; nj < 4; nj++) {
            int row = wn_off + nj * 16 + b_row_l;
            ldmx4(bfrag[0][nj], b_s + sw128(row * 128 + b_chk_l * 16));
        }

#pragma unroll
        for (int ks = 0; ks < BK / 16; ks++) {
            const int cur = ks & 1;
            if (ks < BK / 16 - 1) {
                const int nxt = cur ^ 1;
#pragma unroll
                for (int mi = 0; mi < 4; mi++) {
                    int row = wm_off + mi * 16 + a_row_l;
                    ldmx4(afrag[nxt][mi],
                          a_s + sw128(row * 128 + (ks + 1) * 32 + a_chk_l * 16));
                }
#pragma unroll
                for (int nj = 0; nj < 4; nj++) {
                    int row = wn_off + nj * 16 + b_row_l;
                    ldmx4(bfrag[nxt][nj],
                          b_s + sw128(row * 128 + (ks + 1) * 32 + b_chk_l * 16));
                }
            }
#pragma unroll
            for (int mi = 0; mi < 4; mi++)
#pragma unroll
                for (int ni = 0; ni < 8; ni++)
                    mma16816(acc[mi][ni], afrag[cur][mi],
                             &bfrag[cur][ni >> 1][(ni & 1) * 2]);
        }
    }

    // Epilogue: registers -> global, fused bias, float2 stores
#pragma unroll
    for (int mi = 0; mi < 4; mi++) {
        int r0 = bm + wm_off + mi * 16 + (lane >> 2);
#pragma unroll
        for (int ni = 0; ni < 8; ni++) {
            int col  = wn_off + ni * 8 + (lane & 3) * 2;
            float b0 = bias_s[col], b1 = bias_s[col + 1];
            float2 v0 = make_float2(acc[mi][ni][0] + b0, acc[mi][ni][1] + b1);
            float2 v1 = make_float2(acc[mi][ni][2] + b0, acc[mi][ni][3] + b1);
            *reinterpret_cast<float2*>(C + (size_t)r0 * N + bn + col) = v0;
            *reinterpret_cast<float2*>(C + (size_t)(r0 + 8) * N + bn + col) = v1;
        }
    }
}

// ---------------------------------------------------------------------------
// Launch
// ---------------------------------------------------------------------------
extern "C" void kernel_launch(void* const* d_in, const int* in_sizes, int n_in,
                              void* d_out, int out_size) {
    const float* x      = (const float*)d_in[0];
    const int*   q      = (const int*)  d_in[1];
    const float* scales = (const float*)d_in[2];
    const float* bias   = (const float*)d_in[3];
    float*       out    = (float*)d_out;

    const int O = in_sizes[3];                 // 4096
    const int K = in_sizes[1] / O;             // 4096
    const int M = in_sizes[0] / K;             // 4096
    const int N = O;

    int nx_chunks = (int)((size_t)M * K / 8);
    int nq_chunks = O * (K >> 3);
    int total = nx_chunks + nq_chunks;
    prep_kernel<<<(total + 255) / 256, 256>>>(x, q, scales, nx_chunks, O, K);

    cudaFuncSetAttribute(gemm_mma_kernel,
                         cudaFuncAttributeMaxDynamicSharedMemorySize, SMEM_TOTAL);
    dim3 grid(N / BN, M / BM);
    gemm_mma_kernel<<<grid, THREADS, SMEM_TOTAL>>>(bias, out, M, N, K);
}